// round 3
// baseline (speedup 1.0000x reference)
#include <cuda_runtime.h>
#include <cuda_bf16.h>
#include <math.h>
#include <float.h>

// Problem constants
#define BATCH 2
#define TT    8
#define NN    10000
#define DD    128
#define EE    320000
#define LL    2
#define G3    384
#define ETOT  (EE + NN)   // edges + self loops

#define CDIV(a,b) (((a)+(b)-1)/(b))

// ---------------- scratch (device globals; no allocations allowed) ----------------
__device__ float g_act[BATCH * NN * DD];     // layer-0 activation output
__device__ float g_mm [BATCH * NN * DD];     // GEMM result (pre-propagate)
__device__ float g_W  [LL * BATCH * DD * DD];// evolving weights, layout [c][b][i][j]
__device__ float g_wihT[LL * DD * G3];       // transposed GRU weights [c][k][q]
__device__ float g_whhT[LL * DD * G3];
__device__ float g_deg[NN];                  // degree, then dinv in-place
__device__ int   g_cnt[NN];
__device__ int   g_indptr[NN + 1];
__device__ int   g_cursor[NN];
__device__ int   g_src[ETOT];
__device__ int   g_tgt[ETOT];
__device__ float g_wn [ETOT];
__device__ int   g_bsrc[ETOT];               // CSR-bucketed sources
__device__ float g_bw  [ETOT];               // CSR-bucketed normalized weights
__device__ float g_scores[BATCH * NN];
__device__ int   g_topidx[BATCH * DD];
__device__ float g_toptv [BATCH * DD];
__device__ int   g_is64;

// ---------------- preprocessing kernels ----------------

// Detect whether edge_index is int64 or int32: if int64, every high 32-bit word is 0.
__global__ void k_detect(const void* ei) {
    __shared__ int flag;
    if (threadIdx.x == 0) flag = 0;
    __syncthreads();
    const int* w = (const int*)ei;
    for (int i = threadIdx.x; i < 1024; i += blockDim.x) {
        if (w[2 * i + 1] != 0) flag = 1;
    }
    __syncthreads();
    if (threadIdx.x == 0) g_is64 = flag ? 0 : 1;
}

__global__ void k_zero() {
    int i = blockIdx.x * blockDim.x + threadIdx.x;
    if (i < NN) { g_deg[i] = 0.f; g_cnt[i] = 0; }
}

__global__ void k_convert(const void* ei) {
    int e = blockIdx.x * blockDim.x + threadIdx.x;
    if (e >= ETOT) return;
    int s, t;
    if (e < EE) {
        if (g_is64) {
            const long long* p = (const long long*)ei;
            s = (int)p[e]; t = (int)p[EE + e];
        } else {
            const int* p = (const int*)ei;
            s = p[e]; t = p[EE + e];
        }
    } else {
        s = t = e - EE;  // self loop
    }
    g_src[e] = s; g_tgt[e] = t;
}

__global__ void k_deg(const float* __restrict__ ew) {
    int e = blockIdx.x * blockDim.x + threadIdx.x;
    if (e >= ETOT) return;
    float w = (e < EE) ? ew[e] : 1.0f;
    int t = g_tgt[e];
    atomicAdd(&g_deg[t], w);
    atomicAdd(&g_cnt[t], 1);
}

__global__ void k_dinv() {
    int i = blockIdx.x * blockDim.x + threadIdx.x;
    if (i < NN) {
        float d = g_deg[i];
        g_deg[i] = (d > 0.f) ? (1.0f / sqrtf(d)) : 0.f;
    }
}

__global__ void k_wn(const float* __restrict__ ew) {
    int e = blockIdx.x * blockDim.x + threadIdx.x;
    if (e >= ETOT) return;
    float w = (e < EE) ? ew[e] : 1.0f;
    g_wn[e] = g_deg[g_src[e]] * w * g_deg[g_tgt[e]];  // g_deg holds dinv now
}

__global__ void k_scan() {
    __shared__ int part[1024];
    int tid = threadIdx.x;
    const int CH = CDIV(NN, 1024);
    int s0 = tid * CH;
    int sum = 0;
    for (int i = 0; i < CH; i++) {
        int idx = s0 + i;
        if (idx < NN) sum += g_cnt[idx];
    }
    part[tid] = sum;
    __syncthreads();
    if (tid == 0) {
        int run = 0;
        for (int i = 0; i < 1024; i++) { int t = part[i]; part[i] = run; run += t; }
        g_indptr[NN] = run;
    }
    __syncthreads();
    int off = part[tid];
    for (int i = 0; i < CH; i++) {
        int idx = s0 + i;
        if (idx < NN) {
            g_indptr[idx] = off;
            g_cursor[idx] = off;
            off += g_cnt[idx];
        }
    }
}

__global__ void k_bucket() {
    int e = blockIdx.x * blockDim.x + threadIdx.x;
    if (e >= ETOT) return;
    int t = g_tgt[e];
    int p = atomicAdd(&g_cursor[t], 1);
    g_bsrc[p] = g_src[e];
    g_bw[p]   = g_wn[e];
}

__global__ void k_initW(const float* __restrict__ W0) {
    int idx = blockIdx.x * blockDim.x + threadIdx.x;
    if (idx >= LL * BATCH * DD * DD) return;
    int c  = idx / (BATCH * DD * DD);
    int ij = idx % (DD * DD);
    g_W[idx] = W0[c * DD * DD + ij];
}

__global__ void k_transpose(const float* __restrict__ wih, const float* __restrict__ whh) {
    int idx = blockIdx.x * blockDim.x + threadIdx.x;
    if (idx >= LL * G3 * DD) return;
    int c = idx / (G3 * DD);
    int r = idx % (G3 * DD);
    int q = r / DD;
    int k = r % DD;
    g_wihT[(c * DD + k) * G3 + q] = wih[idx];
    g_whhT[(c * DD + k) * G3 + q] = whh[idx];
}

// ---------------- per-step kernels ----------------

// scores[b,n] = dot(in[b,n,:], p)   (unnormalized; normalization folded into tanh later)
__global__ void k_scores(const float* __restrict__ in, long bstride,
                         const float* __restrict__ pc) {
    int b    = blockIdx.y;
    int warp = threadIdx.x >> 5, lane = threadIdx.x & 31;
    int node = blockIdx.x * 8 + warp;
    if (node >= NN) return;
    const float4* xr = (const float4*)(in + (long)b * bstride + (long)node * DD);
    float4 xv = xr[lane];
    float4 pv = ((const float4*)pc)[lane];
    float s = xv.x * pv.x + xv.y * pv.y + xv.z * pv.z + xv.w * pv.w;
    #pragma unroll
    for (int o = 16; o; o >>= 1) s += __shfl_down_sync(0xffffffffu, s, o);
    if (lane == 0) g_scores[b * NN + node] = s;
}

// Exact top-128 (sorted desc, ties -> smallest index first, matching jax.lax.top_k)
__global__ void k_topk(const float* __restrict__ pc) {
    int b = blockIdx.x;
    int tid = threadIdx.x;
    __shared__ float s[NN];
    __shared__ float rv[32];
    __shared__ int   ri[32];
    __shared__ float s_invn;
    if (tid == 0) {
        float acc = 0.f;
        for (int i = 0; i < DD; i++) { float v = pc[i]; acc += v * v; }
        s_invn = 1.0f / sqrtf(acc);
    }
    for (int i = tid; i < NN; i += 1024) s[i] = g_scores[b * NN + i];
    __syncthreads();
    for (int it = 0; it < DD; it++) {
        float v = -FLT_MAX; int vi = NN;
        for (int i = tid; i < NN; i += 1024) {
            float x = s[i];
            if (x > v) { v = x; vi = i; }
        }
        #pragma unroll
        for (int o = 16; o; o >>= 1) {
            float v2 = __shfl_down_sync(0xffffffffu, v, o);
            int   i2 = __shfl_down_sync(0xffffffffu, vi, o);
            if (v2 > v || (v2 == v && i2 < vi)) { v = v2; vi = i2; }
        }
        if ((tid & 31) == 0) { rv[tid >> 5] = v; ri[tid >> 5] = vi; }
        __syncthreads();
        if (tid < 32) {
            v = rv[tid]; vi = ri[tid];
            #pragma unroll
            for (int o = 16; o; o >>= 1) {
                float v2 = __shfl_down_sync(0xffffffffu, v, o);
                int   i2 = __shfl_down_sync(0xffffffffu, vi, o);
                if (v2 > v || (v2 == v && i2 < vi)) { v = v2; vi = i2; }
            }
            if (tid == 0) {
                g_topidx[b * DD + it] = vi;
                g_toptv [b * DD + it] = tanhf(v * s_invn);
                s[vi] = -FLT_MAX;
            }
        }
        __syncthreads();
    }
}

// GRU cell: each block handles 8 columns (j) of W[b]; thread h = hidden index.
__global__ void k_gru(const float* __restrict__ in, long bstride, int c,
                      const float* __restrict__ bih, const float* __restrict__ bhh) {
    int b = blockIdx.y;
    int h = threadIdx.x;
    int colBase = blockIdx.x * 8;
    __shared__ float xg[8][DD];
    __shared__ float hg[8][DD];
    float* Wl = g_W + ((long)c * BATCH + b) * DD * DD;
    #pragma unroll
    for (int cc = 0; cc < 8; cc++) {
        int col = colBase + cc;
        int node = g_topidx[b * DD + col];
        float tv = g_toptv[b * DD + col];
        xg[cc][h] = in[(long)b * bstride + (long)node * DD + h] * tv;
        hg[cc][h] = Wl[h * DD + col];
    }
    __syncthreads();
    const float* WI = g_wihT + (long)c * DD * G3;
    const float* WH = g_whhT + (long)c * DD * G3;
    float ir[8] = {0}, iz[8] = {0}, in_[8] = {0};
    float hr[8] = {0}, hz[8] = {0}, hn[8] = {0};
    for (int k = 0; k < DD; k++) {
        float a0 = WI[k * G3 + h], a1 = WI[k * G3 + 128 + h], a2 = WI[k * G3 + 256 + h];
        float b0 = WH[k * G3 + h], b1 = WH[k * G3 + 128 + h], b2 = WH[k * G3 + 256 + h];
        #pragma unroll
        for (int cc = 0; cc < 8; cc++) {
            float xv = xg[cc][k], hv = hg[cc][k];
            ir[cc] += xv * a0; iz[cc] += xv * a1; in_[cc] += xv * a2;
            hr[cc] += hv * b0; hz[cc] += hv * b1; hn[cc] += hv * b2;
        }
    }
    float bi0 = bih[h], bi1 = bih[128 + h], bi2 = bih[256 + h];
    float bh0 = bhh[h], bh1 = bhh[128 + h], bh2 = bhh[256 + h];
    #pragma unroll
    for (int cc = 0; cc < 8; cc++) {
        float r = 1.f / (1.f + expf(-((ir[cc] + bi0) + (hr[cc] + bh0))));
        float z = 1.f / (1.f + expf(-((iz[cc] + bi1) + (hz[cc] + bh1))));
        float n = tanhf((in_[cc] + bi2) + r * (hn[cc] + bh2));
        float hnew = (1.f - z) * n + z * hg[cc][h];
        Wl[h * DD + colBase + cc] = hnew;
    }
}

// o[b] = in[b] @ W[c][b]   ([NN,128] @ [128,128])
__global__ void k_gemm(const float* __restrict__ in, long bstride, int c,
                       float* __restrict__ o) {
    int b = blockIdx.y;
    const float* W = g_W + ((long)c * BATCH + b) * DD * DD;
    const float* X = in + (long)b * bstride;
    int rowBase = blockIdx.x * 32;
    int tid = threadIdx.x;
    int ty = tid >> 5, tx = tid & 31;
    __shared__ float xs[32][32];
    __shared__ float ws[32 * DD];
    float4 acc[4];
    #pragma unroll
    for (int i = 0; i < 4; i++) acc[i] = make_float4(0.f, 0.f, 0.f, 0.f);

    for (int kt = 0; kt < 4; kt++) {
        for (int l = tid; l < 32 * 32; l += 256) {
            int r = l >> 5, k = l & 31;
            int row = rowBase + r;
            xs[r][k] = (row < NN) ? X[(long)row * DD + kt * 32 + k] : 0.f;
        }
        const float4* W4 = (const float4*)(W + kt * 32 * DD);
        float4* ws4 = (float4*)ws;
        for (int l = tid; l < 32 * 32; l += 256) ws4[l] = W4[l];
        __syncthreads();
        #pragma unroll 8
        for (int k = 0; k < 32; k++) {
            float4 wv = ((float4*)ws)[k * 32 + tx];
            #pragma unroll
            for (int i = 0; i < 4; i++) {
                float xv = xs[ty * 4 + i][k];
                acc[i].x += xv * wv.x;
                acc[i].y += xv * wv.y;
                acc[i].z += xv * wv.z;
                acc[i].w += xv * wv.w;
            }
        }
        __syncthreads();
    }
    #pragma unroll
    for (int i = 0; i < 4; i++) {
        int row = rowBase + ty * 4 + i;
        if (row < NN)
            ((float4*)o)[((long)b * NN + row) * 32 + tx] = acc[i];
    }
}

// CSR gather propagate + bias + relu
__global__ void k_prop(const float* __restrict__ o, float* __restrict__ outp,
                       const float* __restrict__ bias) {
    int n = blockIdx.x, b = blockIdx.y, f = threadIdx.x;
    int s = g_indptr[n], e = g_indptr[n + 1];
    const float* ob = o + (long)b * NN * DD;
    float acc = 0.f;
    for (int j = s; j < e; j++) {
        acc += ob[(long)g_bsrc[j] * DD + f] * g_bw[j];
    }
    outp[((long)b * NN + n) * DD + f] = fmaxf(acc + bias[f], 0.f);
}

// ---------------- launcher ----------------
extern "C" void kernel_launch(void* const* d_in, const int* in_sizes, int n_in,
                              void* d_out, int out_size) {
    const float* x    = (const float*)d_in[0];
    const void*  ei   = d_in[1];
    const float* ew   = (const float*)d_in[2];
    const float* W0   = (const float*)d_in[3];
    const float* p    = (const float*)d_in[4];
    const float* wih  = (const float*)d_in[5];
    const float* whh  = (const float*)d_in[6];
    const float* bih  = (const float*)d_in[7];
    const float* bhh  = (const float*)d_in[8];
    const float* bias = (const float*)d_in[9];
    float* out = (float*)d_out;

    float *p_act = nullptr, *p_mm = nullptr;
    cudaGetSymbolAddress((void**)&p_act, g_act);
    cudaGetSymbolAddress((void**)&p_mm,  g_mm);

    // graph preprocessing (once per launch, amortized over 9 propagates)
    k_detect<<<1, 256>>>(ei);
    k_zero<<<CDIV(NN, 256), 256>>>();
    k_convert<<<CDIV(ETOT, 256), 256>>>(ei);
    k_deg<<<CDIV(ETOT, 256), 256>>>(ew);
    k_dinv<<<CDIV(NN, 256), 256>>>();
    k_wn<<<CDIV(ETOT, 256), 256>>>(ew);
    k_scan<<<1, 1024>>>();
    k_bucket<<<CDIV(ETOT, 256), 256>>>();
    k_initW<<<CDIV(LL * BATCH * DD * DD, 256), 256>>>(W0);
    k_transpose<<<CDIV(LL * G3 * DD, 256), 256>>>(wih, whh);

    for (int t = 0; t < TT; t++) {
        for (int c = 0; c < LL; c++) {
            const float* in = (c == 0) ? (x + (long)t * NN * DD) : p_act;
            long bstr = (c == 0) ? (long)TT * NN * DD : (long)NN * DD;

            k_scores<<<dim3(CDIV(NN, 8), BATCH), 256>>>(in, bstr, p + c * DD);
            k_topk<<<BATCH, 1024>>>(p + c * DD);
            k_gru<<<dim3(DD / 8, BATCH), DD>>>(in, bstr, c, bih + c * G3, bhh + c * G3);

            // Layer-1 activations only feed the *output* at the final timestep;
            // skip its GEMM+propagate for t < T-1 (W-evolution only needs topk+GRU).
            if (c == 0 || t == TT - 1) {
                k_gemm<<<dim3(CDIV(NN, 32), BATCH), 256>>>(in, bstr, c, p_mm);
                float* op = (c == 0) ? p_act : out;
                k_prop<<<dim3(NN, BATCH), DD>>>(p_mm, op, bias + c * DD);
            }
        }
    }
}

// round 8
// speedup vs baseline: 2.3066x; 2.3066x over previous
#include <cuda_runtime.h>
#include <cuda_bf16.h>
#include <math.h>
#include <float.h>

// Problem constants
#define BATCH 2
#define TT    8
#define NN    10000
#define DD    128
#define EE    320000
#define LL    2
#define G3    384
#define ETOT  (EE + NN)   // edges + self loops

#define CDIV(a,b) (((a)+(b)-1)/(b))

// ---------------- scratch (device globals; no allocations allowed) ----------------
__device__ float g_act[BATCH * NN * DD];     // layer-0 activation output
__device__ float g_mm [BATCH * NN * DD];     // GEMM result (pre-propagate)
__device__ float g_W  [LL * BATCH * DD * DD];// evolving weights, layout [c][b][i][j]
__device__ float g_wihT[LL * DD * G3];       // transposed GRU weights [c][k][q]
__device__ float g_whhT[LL * DD * G3];
__device__ float g_deg[NN];                  // degree, then dinv in-place
__device__ int   g_cnt[NN];
__device__ int   g_indptr[NN + 1];
__device__ int   g_cursor[NN];
__device__ int   g_src[ETOT];
__device__ int   g_tgt[ETOT];
__device__ float g_wn [ETOT];
__device__ int   g_bsrc[ETOT];               // CSR-bucketed sources
__device__ float g_bw  [ETOT];               // CSR-bucketed normalized weights
__device__ float g_scores[BATCH * NN];
__device__ int   g_topidx[BATCH * DD];
__device__ float g_toptv [BATCH * DD];
__device__ int   g_is64;

// ---------------- preprocessing kernels ----------------

// Detect whether edge_index is int64 or int32: if int64, every high 32-bit word is 0.
__global__ void k_detect(const void* ei) {
    __shared__ int flag;
    if (threadIdx.x == 0) flag = 0;
    __syncthreads();
    const int* w = (const int*)ei;
    for (int i = threadIdx.x; i < 1024; i += blockDim.x) {
        if (w[2 * i + 1] != 0) flag = 1;
    }
    __syncthreads();
    if (threadIdx.x == 0) g_is64 = flag ? 0 : 1;
}

__global__ void k_zero() {
    int i = blockIdx.x * blockDim.x + threadIdx.x;
    if (i < NN) { g_deg[i] = 0.f; g_cnt[i] = 0; }
}

__global__ void k_convert(const void* ei) {
    int e = blockIdx.x * blockDim.x + threadIdx.x;
    if (e >= ETOT) return;
    int s, t;
    if (e < EE) {
        if (g_is64) {
            const long long* p = (const long long*)ei;
            s = (int)p[e]; t = (int)p[EE + e];
        } else {
            const int* p = (const int*)ei;
            s = p[e]; t = p[EE + e];
        }
    } else {
        s = t = e - EE;  // self loop
    }
    g_src[e] = s; g_tgt[e] = t;
}

__global__ void k_deg(const float* __restrict__ ew) {
    int e = blockIdx.x * blockDim.x + threadIdx.x;
    if (e >= ETOT) return;
    float w = (e < EE) ? ew[e] : 1.0f;
    int t = g_tgt[e];
    atomicAdd(&g_deg[t], w);
    atomicAdd(&g_cnt[t], 1);
}

__global__ void k_dinv() {
    int i = blockIdx.x * blockDim.x + threadIdx.x;
    if (i < NN) {
        float d = g_deg[i];
        g_deg[i] = (d > 0.f) ? (1.0f / sqrtf(d)) : 0.f;
    }
}

__global__ void k_wn(const float* __restrict__ ew) {
    int e = blockIdx.x * blockDim.x + threadIdx.x;
    if (e >= ETOT) return;
    float w = (e < EE) ? ew[e] : 1.0f;
    g_wn[e] = g_deg[g_src[e]] * w * g_deg[g_tgt[e]];  // g_deg holds dinv now
}

__global__ void k_scan() {
    __shared__ int part[1024];
    int tid = threadIdx.x;
    const int CH = CDIV(NN, 1024);
    int s0 = tid * CH;
    int sum = 0;
    for (int i = 0; i < CH; i++) {
        int idx = s0 + i;
        if (idx < NN) sum += g_cnt[idx];
    }
    part[tid] = sum;
    __syncthreads();
    if (tid == 0) {
        int run = 0;
        for (int i = 0; i < 1024; i++) { int t = part[i]; part[i] = run; run += t; }
        g_indptr[NN] = run;
    }
    __syncthreads();
    int off = part[tid];
    for (int i = 0; i < CH; i++) {
        int idx = s0 + i;
        if (idx < NN) {
            g_indptr[idx] = off;
            g_cursor[idx] = off;
            off += g_cnt[idx];
        }
    }
}

__global__ void k_bucket() {
    int e = blockIdx.x * blockDim.x + threadIdx.x;
    if (e >= ETOT) return;
    int t = g_tgt[e];
    int p = atomicAdd(&g_cursor[t], 1);
    g_bsrc[p] = g_src[e];
    g_bw[p]   = g_wn[e];
}

__global__ void k_initW(const float* __restrict__ W0) {
    int idx = blockIdx.x * blockDim.x + threadIdx.x;
    if (idx >= LL * BATCH * DD * DD) return;
    int c  = idx / (BATCH * DD * DD);
    int ij = idx % (DD * DD);
    g_W[idx] = W0[c * DD * DD + ij];
}

__global__ void k_transpose(const float* __restrict__ wih, const float* __restrict__ whh) {
    int idx = blockIdx.x * blockDim.x + threadIdx.x;
    if (idx >= LL * G3 * DD) return;
    int c = idx / (G3 * DD);
    int r = idx % (G3 * DD);
    int q = r / DD;
    int k = r % DD;
    g_wihT[(c * DD + k) * G3 + q] = wih[idx];
    g_whhT[(c * DD + k) * G3 + q] = whh[idx];
}

// ---------------- per-step kernels ----------------

// scores[b,n] = dot(in[b,n,:], p)   (unnormalized; normalization folded into tanh later)
__global__ void k_scores(const float* __restrict__ in, long bstride,
                         const float* __restrict__ pc) {
    int b    = blockIdx.y;
    int warp = threadIdx.x >> 5, lane = threadIdx.x & 31;
    int node = blockIdx.x * 8 + warp;
    if (node >= NN) return;
    const float4* xr = (const float4*)(in + (long)b * bstride + (long)node * DD);
    float4 xv = xr[lane];
    float4 pv = ((const float4*)pc)[lane];
    float s = xv.x * pv.x + xv.y * pv.y + xv.z * pv.z + xv.w * pv.w;
    #pragma unroll
    for (int o = 16; o; o >>= 1) s += __shfl_down_sync(0xffffffffu, s, o);
    if (lane == 0) g_scores[b * NN + node] = s;
}

// Exact top-128 via 4-pass byte radix-select + bitonic sort of candidates.
// Matches jax.lax.top_k semantics: sorted desc, ties -> smallest index first.
#define CAND_MAX 512
__global__ void k_topk(const float* __restrict__ pc) {
    int b   = blockIdx.x;
    int tid = threadIdx.x;
    __shared__ unsigned s_u[NN];
    __shared__ int hist[256];
    __shared__ int suf[256];
    __shared__ unsigned long long cand[CAND_MAX];
    __shared__ int sh_v, sh_krem, sh_cnt;
    __shared__ unsigned sh_prefix;
    __shared__ float s_invn;

    if (tid == 0) {
        float acc = 0.f;
        for (int i = 0; i < DD; i++) { float v = pc[i]; acc += v * v; }
        s_invn = 1.0f / sqrtf(acc);
        sh_krem = DD;
        sh_prefix = 0u;
        sh_cnt = 0;
    }
    // load + monotone transform (float order -> unsigned order)
    for (int i = tid; i < NN; i += 1024) {
        unsigned u = __float_as_uint(g_scores[b * NN + i]);
        u = (u & 0x80000000u) ? ~u : (u | 0x80000000u);
        s_u[i] = u;
    }
    __syncthreads();

    // 4 radix passes, MSB byte first
    for (int pass = 0; pass < 4; pass++) {
        int shift = 24 - 8 * pass;
        if (tid < 256) hist[tid] = 0;
        __syncthreads();
        unsigned pref = sh_prefix;
        for (int i = tid; i < NN; i += 1024) {
            unsigned u = s_u[i];
            bool m = (pass == 0) || ((u >> (shift + 8)) == pref);
            if (m) atomicAdd(&hist[(u >> shift) & 0xFF], 1);
        }
        __syncthreads();
        if (tid < 256) suf[tid] = hist[tid];
        __syncthreads();
        // inclusive suffix scan over 256 bins
        for (int off = 1; off < 256; off <<= 1) {
            int v = 0;
            if (tid < 256 && tid + off < 256) v = suf[tid + off];
            __syncthreads();
            if (tid < 256) suf[tid] += v;
            __syncthreads();
        }
        if (tid < 256) {
            int gt = suf[tid] - hist[tid];   // strictly greater than this bin
            int krem = sh_krem;
            if (gt < krem && gt + hist[tid] >= krem) sh_v = tid;  // unique
        }
        __syncthreads();
        if (tid == 0) {
            int v = sh_v;
            sh_krem -= (suf[v] - hist[v]);
            sh_prefix = (sh_prefix << 8) | (unsigned)v;
        }
        __syncthreads();
    }
    unsigned uthr = sh_prefix;  // exact k-th largest key

    // gather candidates >= threshold
    for (int i = tid; i < NN; i += 1024) {
        unsigned u = s_u[i];
        if (u >= uthr) {
            int p = atomicAdd(&sh_cnt, 1);
            if (p < CAND_MAX)
                cand[p] = ((unsigned long long)u << 32) |
                          (unsigned long long)(0xFFFFFFFFu - (unsigned)i);
        }
    }
    __syncthreads();
    int cnt = min(sh_cnt, CAND_MAX);
    int P = 256; while (P < cnt) P <<= 1;   // P in {256, 512}
    for (int i = cnt + tid; i < P; i += 1024) cand[i] = 0ULL;
    __syncthreads();

    // bitonic sort descending over P keys
    for (int k2 = 2; k2 <= P; k2 <<= 1) {
        for (int j = k2 >> 1; j > 0; j >>= 1) {
            for (int i = tid; i < P; i += 1024) {
                int l = i ^ j;
                if (l > i) {
                    unsigned long long a = cand[i], bb = cand[l];
                    bool desc = ((i & k2) == 0);
                    if (desc ? (a < bb) : (a > bb)) { cand[i] = bb; cand[l] = a; }
                }
            }
            __syncthreads();
        }
    }

    if (tid < DD) {
        unsigned long long key = cand[tid];
        unsigned u = (unsigned)(key >> 32);
        u = (u & 0x80000000u) ? (u & 0x7FFFFFFFu) : ~u;  // inverse transform
        float f = __uint_as_float(u);
        int idx = (int)(0xFFFFFFFFu - (unsigned)(key & 0xFFFFFFFFu));
        g_topidx[b * DD + tid] = idx;
        g_toptv [b * DD + tid] = tanhf(f * s_invn);
    }
}

// GRU cell: each block handles 8 columns (j) of W[b]; thread h = hidden index.
__global__ void k_gru(const float* __restrict__ in, long bstride, int c,
                      const float* __restrict__ bih, const float* __restrict__ bhh) {
    int b = blockIdx.y;
    int h = threadIdx.x;
    int colBase = blockIdx.x * 8;
    __shared__ float xg[8][DD];
    __shared__ float hg[8][DD];
    float* Wl = g_W + ((long)c * BATCH + b) * DD * DD;
    #pragma unroll
    for (int cc = 0; cc < 8; cc++) {
        int col = colBase + cc;
        int node = g_topidx[b * DD + col];
        float tv = g_toptv[b * DD + col];
        xg[cc][h] = in[(long)b * bstride + (long)node * DD + h] * tv;
        hg[cc][h] = Wl[h * DD + col];
    }
    __syncthreads();
    const float* WI = g_wihT + (long)c * DD * G3;
    const float* WH = g_whhT + (long)c * DD * G3;
    float ir[8] = {0}, iz[8] = {0}, in_[8] = {0};
    float hr[8] = {0}, hz[8] = {0}, hn[8] = {0};
    for (int k = 0; k < DD; k++) {
        float a0 = WI[k * G3 + h], a1 = WI[k * G3 + 128 + h], a2 = WI[k * G3 + 256 + h];
        float b0 = WH[k * G3 + h], b1 = WH[k * G3 + 128 + h], b2 = WH[k * G3 + 256 + h];
        #pragma unroll
        for (int cc = 0; cc < 8; cc++) {
            float xv = xg[cc][k], hv = hg[cc][k];
            ir[cc] += xv * a0; iz[cc] += xv * a1; in_[cc] += xv * a2;
            hr[cc] += hv * b0; hz[cc] += hv * b1; hn[cc] += hv * b2;
        }
    }
    float bi0 = bih[h], bi1 = bih[128 + h], bi2 = bih[256 + h];
    float bh0 = bhh[h], bh1 = bhh[128 + h], bh2 = bhh[256 + h];
    #pragma unroll
    for (int cc = 0; cc < 8; cc++) {
        float r = 1.f / (1.f + expf(-((ir[cc] + bi0) + (hr[cc] + bh0))));
        float z = 1.f / (1.f + expf(-((iz[cc] + bi1) + (hz[cc] + bh1))));
        float n = tanhf((in_[cc] + bi2) + r * (hn[cc] + bh2));
        float hnew = (1.f - z) * n + z * hg[cc][h];
        Wl[h * DD + colBase + cc] = hnew;
    }
}

// o[b] = in[b] @ W[c][b]   ([NN,128] @ [128,128])
// X tile stored transposed + XOR-swizzled so the mainloop does 1 broadcast
// float4 LDS for X + 1 conflict-free float4 LDS for W per k (LDS no longer binding).
__global__ void k_gemm(const float* __restrict__ in, long bstride, int c,
                       float* __restrict__ o) {
    int b = blockIdx.y;
    const float* W = g_W + ((long)c * BATCH + b) * DD * DD;
    const float* X = in + (long)b * bstride;
    int rowBase = blockIdx.x * 32;
    int tid = threadIdx.x;
    int ty = tid >> 5, tx = tid & 31;
    __shared__ float xs[32 * 32];   // [k][row], row-groups swizzled by k
    __shared__ float ws[32 * DD];
    float4 acc[4];
    #pragma unroll
    for (int i = 0; i < 4; i++) acc[i] = make_float4(0.f, 0.f, 0.f, 0.f);

    for (int kt = 0; kt < 4; kt++) {
        // X tile: thread loads float4 of row (tid>>3), k-chunk (tid&7), stores transposed
        {
            int r  = tid >> 3;
            int c8 = tid & 7;
            int row = rowBase + r;
            float4 xv = make_float4(0.f, 0.f, 0.f, 0.f);
            if (row < NN)
                xv = *(const float4*)&X[(long)row * DD + kt * 32 + c8 * 4];
            int g = r >> 2, rl = r & 3;
            float v[4] = {xv.x, xv.y, xv.z, xv.w};
            #pragma unroll
            for (int i = 0; i < 4; i++) {
                int k = c8 * 4 + i;
                xs[k * 32 + (((g ^ (k & 7)) << 2) | rl)] = v[i];
            }
        }
        const float4* W4 = (const float4*)(W + kt * 32 * DD);
        float4* ws4 = (float4*)ws;
        for (int l = tid; l < 32 * 32; l += 256) ws4[l] = W4[l];
        __syncthreads();
        #pragma unroll
        for (int k = 0; k < 32; k++) {
            float4 wv = ((float4*)ws)[k * 32 + tx];
            float4 xv = *(float4*)&xs[k * 32 + ((ty ^ (k & 7)) << 2)];
            acc[0].x += xv.x * wv.x; acc[0].y += xv.x * wv.y; acc[0].z += xv.x * wv.z; acc[0].w += xv.x * wv.w;
            acc[1].x += xv.y * wv.x; acc[1].y += xv.y * wv.y; acc[1].z += xv.y * wv.z; acc[1].w += xv.y * wv.w;
            acc[2].x += xv.z * wv.x; acc[2].y += xv.z * wv.y; acc[2].z += xv.z * wv.z; acc[2].w += xv.z * wv.w;
            acc[3].x += xv.w * wv.x; acc[3].y += xv.w * wv.y; acc[3].z += xv.w * wv.z; acc[3].w += xv.w * wv.w;
        }
        __syncthreads();
    }
    #pragma unroll
    for (int i = 0; i < 4; i++) {
        int row = rowBase + ty * 4 + i;
        if (row < NN)
            ((float4*)o)[((long)b * NN + row) * 32 + tx] = acc[i];
    }
}

// CSR gather propagate + bias + relu: warp per node, float4 lanes
__global__ void k_prop(const float* __restrict__ o, float* __restrict__ outp,
                       const float* __restrict__ bias) {
    int warp = threadIdx.x >> 5, lane = threadIdx.x & 31;
    int n = blockIdx.x * 8 + warp;
    int b = blockIdx.y;
    if (n >= NN) return;
    int s = g_indptr[n], e = g_indptr[n + 1];
    const float* ob = o + (long)b * NN * DD;
    float4 acc = make_float4(0.f, 0.f, 0.f, 0.f);
    for (int j = s; j < e; j++) {
        int   src = g_bsrc[j];
        float w   = g_bw[j];
        float4 v = *(const float4*)&ob[(long)src * DD + lane * 4];
        acc.x += w * v.x; acc.y += w * v.y; acc.z += w * v.z; acc.w += w * v.w;
    }
    float4 bv = ((const float4*)bias)[lane];
    acc.x = fmaxf(acc.x + bv.x, 0.f);
    acc.y = fmaxf(acc.y + bv.y, 0.f);
    acc.z = fmaxf(acc.z + bv.z, 0.f);
    acc.w = fmaxf(acc.w + bv.w, 0.f);
    *(float4*)&outp[((long)b * NN + n) * DD + lane * 4] = acc;
}

// ---------------- launcher ----------------
extern "C" void kernel_launch(void* const* d_in, const int* in_sizes, int n_in,
                              void* d_out, int out_size) {
    const float* x    = (const float*)d_in[0];
    const void*  ei   = d_in[1];
    const float* ew   = (const float*)d_in[2];
    const float* W0   = (const float*)d_in[3];
    const float* p    = (const float*)d_in[4];
    const float* wih  = (const float*)d_in[5];
    const float* whh  = (const float*)d_in[6];
    const float* bih  = (const float*)d_in[7];
    const float* bhh  = (const float*)d_in[8];
    const float* bias = (const float*)d_in[9];
    float* out = (float*)d_out;

    float *p_act = nullptr, *p_mm = nullptr;
    cudaGetSymbolAddress((void**)&p_act, g_act);
    cudaGetSymbolAddress((void**)&p_mm,  g_mm);

    // graph preprocessing (once per launch, amortized over 9 propagates)
    k_detect<<<1, 256>>>(ei);
    k_zero<<<CDIV(NN, 256), 256>>>();
    k_convert<<<CDIV(ETOT, 256), 256>>>(ei);
    k_deg<<<CDIV(ETOT, 256), 256>>>(ew);
    k_dinv<<<CDIV(NN, 256), 256>>>();
    k_wn<<<CDIV(ETOT, 256), 256>>>(ew);
    k_scan<<<1, 1024>>>();
    k_bucket<<<CDIV(ETOT, 256), 256>>>();
    k_initW<<<CDIV(LL * BATCH * DD * DD, 256), 256>>>(W0);
    k_transpose<<<CDIV(LL * G3 * DD, 256), 256>>>(wih, whh);

    for (int t = 0; t < TT; t++) {
        for (int c = 0; c < LL; c++) {
            const float* in = (c == 0) ? (x + (long)t * NN * DD) : p_act;
            long bstr = (c == 0) ? (long)TT * NN * DD : (long)NN * DD;

            k_scores<<<dim3(CDIV(NN, 8), BATCH), 256>>>(in, bstr, p + c * DD);
            k_topk<<<BATCH, 1024>>>(p + c * DD);
            k_gru<<<dim3(DD / 8, BATCH), DD>>>(in, bstr, c, bih + c * G3, bhh + c * G3);

            // Layer-1 activations only feed the *output* at the final timestep;
            // skip its GEMM+propagate for t < T-1 (W-evolution only needs topk+GRU).
            if (c == 0 || t == TT - 1) {
                k_gemm<<<dim3(CDIV(NN, 32), BATCH), 256>>>(in, bstr, c, p_mm);
                float* op = (c == 0) ? p_act : out;
                k_prop<<<dim3(NN / 8, BATCH), 256>>>(p_mm, op, bias + c * DD);
            }
        }
    }
}